// round 17
// baseline (speedup 1.0000x reference)
#include <cuda_runtime.h>
#include <cuda_fp16.h>
#include <cstdint>

// Problem constants
constexpr int Nn = 50000;
constexpr int Ee = 800000;
constexpr int Ff = 128;
constexpr int Hh = 256;
constexpr int Cc = 64;

constexpr int SCAN_B = 512;
constexpr int NBLK = (Nn + SCAN_B - 1) / SCAN_B;  // 98

// Scratch (fp16 activations). All zero-initialized at load; state is
// self-cleaning: gather_k zeroes g_cnt, finalize_k zeroes g_acc/g_total.
__device__ __half g_hprime[(size_t)Nn * Ff];   // feature @ W_gcn (unscaled)
__device__ __half g_agg[(size_t)Nn * Ff];
__device__ __half g_hh[(size_t)Nn * Hh];
__device__ float g_deg[Nn];     // dinv
__device__ float g_acc[8];
__device__ int g_cnt[Nn];
__device__ int g_rowptr[Nn];    // post-fill: GLOBAL row end
__device__ int g_esrc[Ee];
__device__ int g_total;         // scan base allocator

// ---------------------------------------------------------------------------
// 4 independent edges/thread for atomic MLP
__global__ void cnt_k(const int* __restrict__ adj) {
    constexpr int Q = Ee / 4;
    int t = blockIdx.x * blockDim.x + threadIdx.x;
    if (t >= Q) return;
    int d0 = adj[Ee + t];
    int d1 = adj[Ee + t + Q];
    int d2 = adj[Ee + t + 2 * Q];
    int d3 = adj[Ee + t + 3 * Q];
    atomicAdd(&g_cnt[d0], 1);
    atomicAdd(&g_cnt[d1], 1);
    atomicAdd(&g_cnt[d2], 1);
    atomicAdd(&g_cnt[d3], 1);
}
// block-local scan + atomic global base (order nondeterministic; harmless)
__global__ void scan1_k() {
    __shared__ int s[SCAN_B];
    __shared__ int sbase;
    int tid = threadIdx.x;
    int i = blockIdx.x * SCAN_B + tid;
    int v = (i < Nn) ? g_cnt[i] : 0;
    s[tid] = v;
    __syncthreads();
#pragma unroll
    for (int off = 1; off < SCAN_B; off <<= 1) {
        int t = (tid >= off) ? s[tid - off] : 0;
        __syncthreads();
        s[tid] += t;
        __syncthreads();
    }
    if (tid == SCAN_B - 1) sbase = atomicAdd(&g_total, s[tid]);
    __syncthreads();
    if (i < Nn) {
        g_rowptr[i] = sbase + s[tid] - v;
        g_deg[i] = rsqrtf((float)(v + 1));
    }
}
// fill: rowptr doubles as cursor (ends at GLOBAL row end); 4 edges/thread
__global__ void fill_k(const int* __restrict__ adj) {
    constexpr int Q = Ee / 4;
    int t = blockIdx.x * blockDim.x + threadIdx.x;
    if (t >= Q) return;
    int s0 = adj[t],         d0 = adj[Ee + t];
    int s1 = adj[t + Q],     d1 = adj[Ee + t + Q];
    int s2 = adj[t + 2 * Q], d2 = adj[Ee + t + 2 * Q];
    int s3 = adj[t + 3 * Q], d3 = adj[Ee + t + 3 * Q];
    int p0 = atomicAdd(&g_rowptr[d0], 1);
    int p1 = atomicAdd(&g_rowptr[d1], 1);
    int p2 = atomicAdd(&g_rowptr[d2], 1);
    int p3 = atomicAdd(&g_rowptr[d3], 1);
    g_esrc[p0] = s0;
    g_esrc[p1] = s1;
    g_esrc[p2] = s2;
    g_esrc[p3] = s3;
}

// ---------------------------------------------------------------------------
__device__ __forceinline__ uint32_t smem_u32(const void* p) {
    uint32_t a;
    asm("{ .reg .u64 t; cvta.to.shared.u64 t, %1; cvt.u32.u64 %0, t; }"
        : "=r"(a) : "l"(p));
    return a;
}
__device__ __forceinline__ void ldsm_x4(uint32_t* r, uint32_t addr) {
    asm volatile("ldmatrix.sync.aligned.m8n8.x4.shared.b16 {%0,%1,%2,%3}, [%4];"
                 : "=r"(r[0]), "=r"(r[1]), "=r"(r[2]), "=r"(r[3]) : "r"(addr));
}
__device__ __forceinline__ void ldsm_x2t(uint32_t* r, uint32_t addr) {
    asm volatile("ldmatrix.sync.aligned.m8n8.x2.trans.shared.b16 {%0,%1}, [%2];"
                 : "=r"(r[0]), "=r"(r[1]) : "r"(addr));
}
__device__ __forceinline__ void mma_f16(float* d, const uint32_t* a, const uint32_t* b) {
    asm volatile(
        "mma.sync.aligned.m16n8k16.row.col.f32.f16.f16.f32 "
        "{%0,%1,%2,%3}, {%4,%5,%6,%7}, {%8,%9}, {%0,%1,%2,%3};"
        : "+f"(d[0]), "+f"(d[1]), "+f"(d[2]), "+f"(d[3])
        : "r"(a[0]), "r"(a[1]), "r"(a[2]), "r"(a[3]), "r"(b[0]), "r"(b[1]));
}
__device__ __forceinline__ uint32_t pack_h2(__half a, __half b) {
    __half2 h = __halves2half2(a, b);
    return *(uint32_t*)&h;
}
__device__ __forceinline__ float4 h4_to_f4(uint2 u) {
    float2 fa = __half22float2(*(__half2*)&u.x);
    float2 fb = __half22float2(*(__half2*)&u.y);
    return make_float4(fa.x, fa.y, fb.x, fb.y);
}
__device__ __forceinline__ uint2 f4_to_h4(float4 v) {
    __half2 a = __floats2half2_rn(v.x, v.y);
    __half2 b = __floats2half2_rn(v.z, v.w);
    uint2 u;
    u.x = *(uint32_t*)&a;
    u.y = *(uint32_t*)&b;
    return u;
}

// ---------------------------------------------------------------------------
// fp16 2-term HMMA GEMM: C = A@B via Ah*(Bh+Bl); A single fp16, B split hi/lo.
// BM=128, BN=64, BK=32, 256 threads, 8 warps (4m x 2n), warp tile 32x32.
// AHALF: 0 -> A fp32 ; 1 -> A fp16
// AXF:   1 -> A'[r][k] = dinv[r]*A[r][k] + abias[k]
// EPI:   1 -> relu(v+bias) -> half C0
//        2 -> plain v -> half C0
//        3 -> v+bias -> fp32 C0 replicated to 3 slices
template <int K, int AHALF, int AXF, int EPI>
__global__ void __launch_bounds__(256)
mmagemm(const void* __restrict__ Ap, const float* __restrict__ B,
        const float* __restrict__ abias, const float* __restrict__ bias,
        void* __restrict__ C0p, int M, int Ncol) {
    constexpr int ASTR = 40;
    constexpr int BSTR = 72;
    __shared__ __align__(16) __half Ash[128 * ASTR];
    __shared__ __align__(16) __half Bsh[32 * BSTR];
    __shared__ __align__(16) __half Bsl[32 * BSTR];

    const int tid = threadIdx.x;
    const int wid = tid >> 5;
    const int lane = tid & 31;
    const int wm = wid & 3;
    const int wn = wid >> 2;
    const int m0 = blockIdx.x * 128;
    const int n0 = blockIdx.y * 64;

    const uint32_t uAs = smem_u32(Ash);
    const uint32_t uBh = smem_u32(Bsh);
    const uint32_t uBl = smem_u32(Bsl);

    const int l15 = lane & 15;
    const int lh = lane >> 4;
    uint32_t aOff[2];
#pragma unroll
    for (int mi = 0; mi < 2; mi++)
        aOff[mi] = uAs + (uint32_t)((wm * 32 + mi * 16 + l15) * (ASTR * 2) + lh * 16);
    const uint32_t bOff = (uint32_t)(l15 * (BSTR * 2) + wn * 64);

    float acc[2][4][4];
#pragma unroll
    for (int mi = 0; mi < 2; mi++)
#pragma unroll
        for (int ni = 0; ni < 4; ni++)
#pragma unroll
            for (int j = 0; j < 4; j++) acc[mi][ni][j] = 0.0f;

    constexpr int NC = K / 32;
#pragma unroll 1
    for (int c = 0; c < NC; c++) {
        const int k0 = c * 32;
        if (c > 0) __syncthreads();
        if (AHALF == 0) {
            const float* A = (const float*)Ap;
#pragma unroll
            for (int it = 0; it < 4; it++) {
                int idx = it * 256 + tid;
                int r = idx >> 3, q = idx & 7;
                int gr = m0 + r;
                float4 v = make_float4(0.f, 0.f, 0.f, 0.f);
                if (gr < M) {
                    v = *(const float4*)(A + (size_t)gr * K + k0 + q * 4);
                    if (AXF) {
                        float sc = g_deg[gr];
                        float4 bb = *(const float4*)(abias + k0 + q * 4);
                        v.x = sc * v.x + bb.x; v.y = sc * v.y + bb.y;
                        v.z = sc * v.z + bb.z; v.w = sc * v.w + bb.w;
                    }
                }
                uint2 u;
                u.x = pack_h2(__float2half_rn(v.x), __float2half_rn(v.y));
                u.y = pack_h2(__float2half_rn(v.z), __float2half_rn(v.w));
                *(uint2*)&Ash[r * ASTR + q * 4] = u;
            }
        } else {
            const __half* A = (const __half*)Ap;
#pragma unroll
            for (int it = 0; it < 2; it++) {
                int idx = it * 256 + tid;
                int r = idx >> 2, q = idx & 3;
                int gr = m0 + r;
                uint4 u = make_uint4(0, 0, 0, 0);
                if (gr < M) {
                    u = *(const uint4*)(A + (size_t)gr * K + k0 + q * 8);
                    if (AXF) {
                        float sc = g_deg[gr];
                        float4 b0 = *(const float4*)(abias + k0 + q * 8);
                        float4 b1 = *(const float4*)(abias + k0 + q * 8 + 4);
                        float4 f0 = h4_to_f4(make_uint2(u.x, u.y));
                        float4 f1 = h4_to_f4(make_uint2(u.z, u.w));
                        f0.x = sc * f0.x + b0.x; f0.y = sc * f0.y + b0.y;
                        f0.z = sc * f0.z + b0.z; f0.w = sc * f0.w + b0.w;
                        f1.x = sc * f1.x + b1.x; f1.y = sc * f1.y + b1.y;
                        f1.z = sc * f1.z + b1.z; f1.w = sc * f1.w + b1.w;
                        uint2 p0 = f4_to_h4(f0), p1 = f4_to_h4(f1);
                        u = make_uint4(p0.x, p0.y, p1.x, p1.y);
                    }
                }
                *(uint4*)&Ash[r * ASTR + q * 8] = u;
            }
        }
#pragma unroll
        for (int it = 0; it < 2; it++) {
            int idx = it * 256 + tid;
            int kk = idx >> 4, n4 = (idx & 15) * 4;
            float4 v = *(const float4*)(B + (size_t)(k0 + kk) * Ncol + n0 + n4);
            __half hx = __float2half_rn(v.x), hy = __float2half_rn(v.y);
            __half hz = __float2half_rn(v.z), hw = __float2half_rn(v.w);
            __half lx = __float2half_rn(v.x - __half2float(hx));
            __half ly = __float2half_rn(v.y - __half2float(hy));
            __half lz = __float2half_rn(v.z - __half2float(hz));
            __half lw = __float2half_rn(v.w - __half2float(hw));
            uint2 uh, ul;
            uh.x = pack_h2(hx, hy); uh.y = pack_h2(hz, hw);
            ul.x = pack_h2(lx, ly); ul.y = pack_h2(lz, lw);
            *(uint2*)&Bsh[kk * BSTR + n4] = uh;
            *(uint2*)&Bsl[kk * BSTR + n4] = ul;
        }
        __syncthreads();

#pragma unroll
        for (int ks = 0; ks < 2; ks++) {
            uint32_t ah[2][4], bh[4][2], bl[4][2];
#pragma unroll
            for (int mi = 0; mi < 2; mi++)
                ldsm_x4(ah[mi], aOff[mi] + ks * 32);
#pragma unroll
            for (int ni = 0; ni < 4; ni++) {
                uint32_t bo = bOff + ks * 16 * (BSTR * 2) + ni * 16;
                ldsm_x2t(bh[ni], uBh + bo);
                ldsm_x2t(bl[ni], uBl + bo);
            }
#pragma unroll
            for (int mi = 0; mi < 2; mi++)
#pragma unroll
                for (int ni = 0; ni < 4; ni++) {
                    mma_f16(acc[mi][ni], ah[mi], bh[ni]);
                    mma_f16(acc[mi][ni], ah[mi], bl[ni]);
                }
        }
    }

    const int g = lane >> 2;
    const int tig = lane & 3;
#pragma unroll
    for (int mi = 0; mi < 2; mi++) {
        int row0 = m0 + wm * 32 + mi * 16 + g;
        int row1 = row0 + 8;
#pragma unroll
        for (int ni = 0; ni < 4; ni++) {
            int col = n0 + wn * 32 + ni * 8 + tig * 2;
            float v0 = acc[mi][ni][0], v1 = acc[mi][ni][1];
            float v2 = acc[mi][ni][2], v3 = acc[mi][ni][3];
            if (EPI == 1 || EPI == 3) {
                float2 b = *(const float2*)(bias + col);
                v0 += b.x; v1 += b.y; v2 += b.x; v3 += b.y;
                if (EPI == 1) {
                    v0 = fmaxf(v0, 0.f); v1 = fmaxf(v1, 0.f);
                    v2 = fmaxf(v2, 0.f); v3 = fmaxf(v3, 0.f);
                }
            }
            if (EPI == 1 || EPI == 2) {
                __half* C = (__half*)C0p;
                if (row0 < M)
                    *(__half2*)(C + (size_t)row0 * Ncol + col) = __floats2half2_rn(v0, v1);
                if (row1 < M)
                    *(__half2*)(C + (size_t)row1 * Ncol + col) = __floats2half2_rn(v2, v3);
            } else {
                float* C = (float*)C0p;
                if (row0 < M) {
                    float* p = C + (size_t)row0 * Ncol + col;
                    *(float2*)p = make_float2(v0, v1);
                    *(float2*)(p + (size_t)Nn * Cc) = make_float2(v0, v1);
                    *(float2*)(p + (size_t)2 * Nn * Cc) = make_float2(v0, v1);
                }
                if (row1 < M) {
                    float* p = C + (size_t)row1 * Ncol + col;
                    *(float2*)p = make_float2(v2, v3);
                    *(float2*)(p + (size_t)Nn * Cc) = make_float2(v2, v3);
                    *(float2*)(p + (size_t)2 * Nn * Cc) = make_float2(v2, v3);
                }
            }
        }
    }
}

// ---------------------------------------------------------------------------
// CSR gather with per-source dinv scaling; zeroes g_cnt[d] for next replay.
// agg[d] = dinv[d]*hprime[d] + sum_s dinv[s]*hprime[s]
__global__ void gather_k() {
    int d = blockIdx.x * 8 + (threadIdx.x >> 5);
    int lane = threadIdx.x & 31;
    if (d >= Nn) return;
    const uint2* hp = (const uint2*)g_hprime;
    float sd = g_deg[d];
    float4 self = h4_to_f4(hp[(size_t)d * 32 + lane]);
    float4 a0, a1, a2, a3;
    a0.x = sd * self.x; a0.y = sd * self.y; a0.z = sd * self.z; a0.w = sd * self.w;
    a1 = make_float4(0.f, 0.f, 0.f, 0.f);
    a2 = make_float4(0.f, 0.f, 0.f, 0.f);
    a3 = make_float4(0.f, 0.f, 0.f, 0.f);
    int cnt = g_cnt[d];
    int end = g_rowptr[d];           // cursor ended at GLOBAL row end
    int beg = end - cnt;
    __syncwarp();
    if (lane == 0) g_cnt[d] = 0;     // self-clean for next call
    int e = beg;
    for (; e + 3 < end; e += 4) {
        int s0 = g_esrc[e], s1 = g_esrc[e + 1], s2 = g_esrc[e + 2], s3 = g_esrc[e + 3];
        float c0 = g_deg[s0], c1 = g_deg[s1], c2 = g_deg[s2], c3 = g_deg[s3];
        float4 v0 = h4_to_f4(hp[(size_t)s0 * 32 + lane]);
        float4 v1 = h4_to_f4(hp[(size_t)s1 * 32 + lane]);
        float4 v2 = h4_to_f4(hp[(size_t)s2 * 32 + lane]);
        float4 v3 = h4_to_f4(hp[(size_t)s3 * 32 + lane]);
        a0.x += c0 * v0.x; a0.y += c0 * v0.y; a0.z += c0 * v0.z; a0.w += c0 * v0.w;
        a1.x += c1 * v1.x; a1.y += c1 * v1.y; a1.z += c1 * v1.z; a1.w += c1 * v1.w;
        a2.x += c2 * v2.x; a2.y += c2 * v2.y; a2.z += c2 * v2.z; a2.w += c2 * v2.w;
        a3.x += c3 * v3.x; a3.y += c3 * v3.y; a3.z += c3 * v3.z; a3.w += c3 * v3.w;
    }
    for (; e < end; e++) {
        int s0 = g_esrc[e];
        float c0 = g_deg[s0];
        float4 v0 = h4_to_f4(hp[(size_t)s0 * 32 + lane]);
        a0.x += c0 * v0.x; a0.y += c0 * v0.y; a0.z += c0 * v0.z; a0.w += c0 * v0.w;
    }
    a0.x += a1.x + a2.x + a3.x;
    a0.y += a1.y + a2.y + a3.y;
    a0.z += a1.z + a2.z + a3.z;
    a0.w += a1.w + a2.w + a3.w;
    ((uint2*)g_agg)[(size_t)d * 32 + lane] = f4_to_h4(a0);
}

// ---------------------------------------------------------------------------
// loss: logits already replicated by gemm3; read slice 0 only.
__global__ void loss_k(const int* __restrict__ label, const int* __restrict__ m0,
                       const int* __restrict__ m1, const int* __restrict__ m2,
                       const float* __restrict__ out) {
    __shared__ float sa[6];
    int tid = threadIdx.x;
    if (tid < 6) sa[tid] = 0.0f;
    __syncthreads();

    int r = blockIdx.x * 8 + (tid >> 5);
    int lane = tid & 31;
    if (r < Nn) {
        const float* row = out + (size_t)r * Cc;
        float x0 = row[lane];
        float x1 = row[lane + 32];

        float m = fmaxf(x0, x1);
#pragma unroll
        for (int off = 16; off >= 1; off >>= 1)
            m = fmaxf(m, __shfl_xor_sync(0xffffffffu, m, off));
        float se = expf(x0 - m) + expf(x1 - m);
#pragma unroll
        for (int off = 16; off >= 1; off >>= 1)
            se += __shfl_xor_sync(0xffffffffu, se, off);
        float lse = m + logf(se);
        int l = label[r];
        float cand = (l & 32) ? x1 : x0;
        float v = __shfl_sync(0xffffffffu, cand, l & 31);
        float loss = lse - v;
        if (lane == 0) {
            float t0 = (m0[r] == 1) ? 1.0f : 0.0f;
            float t1 = (m1[r] == 1) ? 1.0f : 0.0f;
            float t2 = (m2[r] == 1) ? 1.0f : 0.0f;
            atomicAdd(&sa[0], loss * t0);
            atomicAdd(&sa[1], loss * t1);
            atomicAdd(&sa[2], loss * t2);
            atomicAdd(&sa[3], t0);
            atomicAdd(&sa[4], t1);
            atomicAdd(&sa[5], t2);
        }
    }
    __syncthreads();
    if (tid < 6) atomicAdd(&g_acc[tid], sa[tid]);
}

// finalize + self-clean accumulators for the next replay
__global__ void finalize_k(float* __restrict__ out) {
    int k = threadIdx.x;
    float v = 0.f;
    if (k < 3) v = g_acc[k] / g_acc[3 + k];
    __syncthreads();
    if (k < 3) out[(size_t)3 * Nn * Cc + k] = v;
    if (k < 8) g_acc[k] = 0.0f;
    if (k == 8) g_total = 0;
}

// ---------------------------------------------------------------------------
extern "C" void kernel_launch(void* const* d_in, const int* in_sizes, int n_in,
                              void* d_out, int out_size) {
    const float* feature = (const float*)d_in[0];
    const int* adj       = (const int*)d_in[1];
    const int* label     = (const int*)d_in[2];
    const int* tmask     = (const int*)d_in[3];
    const int* dmask     = (const int*)d_in[4];
    const int* temask    = (const int*)d_in[5];
    const float* W_gcn   = (const float*)d_in[6];
    const float* b_gcn   = (const float*)d_in[7];
    const float* W_ff    = (const float*)d_in[8];
    const float* b_ff    = (const float*)d_in[9];
    const float* W_pred  = (const float*)d_in[10];
    const float* b_pred  = (const float*)d_in[11];
    float* out = (float*)d_out;

    void* d_hprime; cudaGetSymbolAddress(&d_hprime, g_hprime);
    void* d_agg;    cudaGetSymbolAddress(&d_agg, g_agg);
    void* d_hh;     cudaGetSymbolAddress(&d_hh, g_hh);

    const int MB = (Nn + 127) / 128;  // 391

    // side stream + events (created once on the eager correctness call)
    static cudaStream_t s2 = nullptr;
    static cudaEvent_t evFork = nullptr, evJoin = nullptr;
    if (!s2) {
        cudaStreamCreateWithFlags(&s2, cudaStreamNonBlocking);
        cudaEventCreateWithFlags(&evFork, cudaEventDisableTiming);
        cudaEventCreateWithFlags(&evJoin, cudaEventDisableTiming);
    }

    // fork: CSR build + dinv on s2, gemm1 on main stream
    cudaEventRecord(evFork, 0);
    cudaStreamWaitEvent(s2, evFork, 0);

    cnt_k<<<(Ee / 4 + 255) / 256, 256, 0, s2>>>(adj);
    scan1_k<<<NBLK, SCAN_B, 0, s2>>>();
    fill_k<<<(Ee / 4 + 255) / 256, 256, 0, s2>>>(adj);

    // gemm1: hprime = feature @ W_gcn (unscaled; dinv applied in gather)
    {
        dim3 grid(MB, Ff / 64);
        mmagemm<128, 0, 0, 2><<<grid, 256>>>(feature, W_gcn, nullptr, nullptr,
                                             d_hprime, Nn, Ff);
    }

    // join
    cudaEventRecord(evJoin, s2);
    cudaStreamWaitEvent(0, evJoin, 0);

    // agg[d] = dinv[d]*hprime[d] + sum dinv[s]*hprime[s]  (+ cnt self-clean)
    gather_k<<<(Nn + 7) / 8, 256>>>();

    // hh = relu((dinv*agg + b_gcn) @ W_ff + b_ff)
    {
        dim3 grid(MB, Hh / 64);
        mmagemm<128, 1, 1, 1><<<grid, 256>>>(d_agg, W_ff, b_gcn, b_ff,
                                             d_hh, Nn, Hh);
    }
    // logits -> 3 slices
    {
        dim3 grid(MB, Cc / 64);
        mmagemm<256, 1, 0, 3><<<grid, 256>>>(d_hh, W_pred, nullptr, b_pred,
                                             out, Nn, Cc);
    }

    loss_k<<<(Nn + 7) / 8, 256>>>(label, tmask, dmask, temask, out);
    finalize_k<<<1, 32>>>(out);
}